// round 12
// baseline (speedup 1.0000x reference)
#include <cuda_runtime.h>
#include <cuda_bf16.h>
#include <cstdint>

// out[s,a] = values[index[s,a]]
// index: int32 [33,554,432], values: float [100], out: float [33,554,432]
//
// Converged HBM-bound gather (~7.4 TB/s goodput). This round probes the last
// untested lever: store policy. Loads stay streaming (__ldcs, zero reuse) but
// stores switch evict-first (__stcs) -> write-back (__stwb): let the 126MB L2
// absorb the 134MB output stream during the kernel instead of forcing early
// DRAM writeback that competes with the index read stream.
//
// Sweep so far (kernel us): MLP=1 41.4 | MLP=4/256t 37.1 | MLP=8 37.5 |
// 512t 38.0 | persistent 38.2 | replicated-table 39.1 | 64t 36.22 |
// 128t+stcs 36.19-36.38 (prev best).

static constexpr int VOCAB_MAX       = 128;
static constexpr int THREADS         = 128;
static constexpr int VEC_PER_THREAD  = 4;                        // 4 x int4 = 16 elems/thread
static constexpr int VEC_PER_BLOCK   = THREADS * VEC_PER_THREAD; // 512 vec4/block

__global__ void __launch_bounds__(THREADS) gather_128t_wb_kernel(
    const int4* __restrict__ idx4,
    const float* __restrict__ values,
    float4* __restrict__ out4,
    int n_vec4,
    int n_values)
{
    __shared__ float s_vals[VOCAB_MAX];
    if (threadIdx.x < n_values) {
        s_vals[threadIdx.x] = values[threadIdx.x];
    }
    __syncthreads();

    int base = blockIdx.x * VEC_PER_BLOCK + threadIdx.x;

    if (base + (VEC_PER_THREAD - 1) * THREADS < n_vec4) {
        // Fast path: every block for this shape (8,388,608 / 512 = 16384).
        int4 v[VEC_PER_THREAD];
        #pragma unroll
        for (int k = 0; k < VEC_PER_THREAD; k++) {
            v[k] = __ldcs(&idx4[base + k * THREADS]);
        }
        #pragma unroll
        for (int k = 0; k < VEC_PER_THREAD; k++) {
            float4 r;
            r.x = s_vals[v[k].x];
            r.y = s_vals[v[k].y];
            r.z = s_vals[v[k].z];
            r.w = s_vals[v[k].w];
            __stwb(&out4[base + k * THREADS], r);   // write-back: L2 buffers the stream
        }
    } else {
        // Guard path (unused for this shape)
        #pragma unroll
        for (int k = 0; k < VEC_PER_THREAD; k++) {
            int i = base + k * THREADS;
            if (i < n_vec4) {
                int4 v = __ldcs(&idx4[i]);
                float4 r;
                r.x = s_vals[v.x];
                r.y = s_vals[v.y];
                r.z = s_vals[v.z];
                r.w = s_vals[v.w];
                __stwb(&out4[i], r);
            }
        }
    }
}

__global__ void gather_tail_kernel(
    const int* __restrict__ idx,
    const float* __restrict__ values,
    float* __restrict__ out,
    int start,
    int n_total)
{
    int i = start + blockIdx.x * blockDim.x + threadIdx.x;
    if (i < n_total) {
        out[i] = values[idx[i]];
    }
}

extern "C" void kernel_launch(void* const* d_in, const int* in_sizes, int n_in,
                              void* d_out, int out_size)
{
    const int* index = (const int*)d_in[0];
    const float* values = (const float*)d_in[1];
    float* out = (float*)d_out;

    int n_total = in_sizes[0];          // 33,554,432
    int n_values = in_sizes[1];         // 100
    int n_vec4 = n_total / 4;           // 8,388,608

    int blocks = (n_vec4 + VEC_PER_BLOCK - 1) / VEC_PER_BLOCK;   // 16384
    gather_128t_wb_kernel<<<blocks, THREADS>>>(
        (const int4*)index, values, (float4*)out, n_vec4, n_values);

    // Tail is 0 for this shape (n_total % 4 == 0); launch only if needed.
    int tail_start = n_vec4 * 4;
    int tail = n_total - tail_start;
    if (tail > 0) {
        int tb = (tail + 255) / 256;
        gather_tail_kernel<<<tb, 256>>>(index, values, out, tail_start, n_total);
    }
}

// round 13
// speedup vs baseline: 1.0043x; 1.0043x over previous
#include <cuda_runtime.h>
#include <cuda_bf16.h>
#include <cstdint>

// out[s,a] = values[index[s,a]]
// index: int32 [33,554,432], values: float [100], out: float [33,554,432]
//
// FINAL (converged, frozen). HBM-bound gather at ~7.4 TB/s goodput
// (~92% of 8 TB/s spec); kernel ~36.2us vs 33.5us absolute traffic floor.
//
// Complete sweep (kernel us):
//   MLP=1 41.4 | MLP=4/256t 37.1-37.4 | MLP=8 37.5 | 512t 38.0
//   persistent 38.2 | replicated-table 39.1 | 64t 36.22
//   128t+stcs 36.19-36.38 (BEST, this config) | 128t+stwb 36.99
// dur_us noise floor ~43.5.
//
// Winning recipe:
//  - 128 threads/block, flat grid 16384 CTAs (smooth L1tex queue pressure,
//    cheap barriers, occ ~85%)
//  - single-copy 512B smem table, one predicated load to fill
//  - MLP = 4 front-batched int4 loads / float4 stores (28 regs)
//  - __ldcs loads + __stcs stores (evict-first on both touch-once streams;
//    write-back stores measured worse: L2 write-allocate evicts index sectors)

static constexpr int VOCAB_MAX       = 128;
static constexpr int THREADS         = 128;
static constexpr int VEC_PER_THREAD  = 4;                        // 4 x int4 = 16 elems/thread
static constexpr int VEC_PER_BLOCK   = THREADS * VEC_PER_THREAD; // 512 vec4/block

__global__ void __launch_bounds__(THREADS) gather_final128_kernel(
    const int4* __restrict__ idx4,
    const float* __restrict__ values,
    float4* __restrict__ out4,
    int n_vec4,
    int n_values)
{
    __shared__ float s_vals[VOCAB_MAX];
    if (threadIdx.x < n_values) {
        s_vals[threadIdx.x] = values[threadIdx.x];
    }
    __syncthreads();

    int base = blockIdx.x * VEC_PER_BLOCK + threadIdx.x;

    if (base + (VEC_PER_THREAD - 1) * THREADS < n_vec4) {
        // Fast path: every block for this shape (8,388,608 / 512 = 16384).
        int4 v[VEC_PER_THREAD];
        #pragma unroll
        for (int k = 0; k < VEC_PER_THREAD; k++) {
            v[k] = __ldcs(&idx4[base + k * THREADS]);
        }
        #pragma unroll
        for (int k = 0; k < VEC_PER_THREAD; k++) {
            float4 r;
            r.x = s_vals[v[k].x];
            r.y = s_vals[v[k].y];
            r.z = s_vals[v[k].z];
            r.w = s_vals[v[k].w];
            __stcs(&out4[base + k * THREADS], r);
        }
    } else {
        // Guard path (unused for this shape)
        #pragma unroll
        for (int k = 0; k < VEC_PER_THREAD; k++) {
            int i = base + k * THREADS;
            if (i < n_vec4) {
                int4 v = __ldcs(&idx4[i]);
                float4 r;
                r.x = s_vals[v.x];
                r.y = s_vals[v.y];
                r.z = s_vals[v.z];
                r.w = s_vals[v.w];
                __stcs(&out4[i], r);
            }
        }
    }
}

__global__ void gather_tail_kernel(
    const int* __restrict__ idx,
    const float* __restrict__ values,
    float* __restrict__ out,
    int start,
    int n_total)
{
    int i = start + blockIdx.x * blockDim.x + threadIdx.x;
    if (i < n_total) {
        out[i] = values[idx[i]];
    }
}

extern "C" void kernel_launch(void* const* d_in, const int* in_sizes, int n_in,
                              void* d_out, int out_size)
{
    const int* index = (const int*)d_in[0];
    const float* values = (const float*)d_in[1];
    float* out = (float*)d_out;

    int n_total = in_sizes[0];          // 33,554,432
    int n_values = in_sizes[1];         // 100
    int n_vec4 = n_total / 4;           // 8,388,608

    int blocks = (n_vec4 + VEC_PER_BLOCK - 1) / VEC_PER_BLOCK;   // 16384
    gather_final128_kernel<<<blocks, THREADS>>>(
        (const int4*)index, values, (float4*)out, n_vec4, n_values);

    // Tail is 0 for this shape (n_total % 4 == 0); launch only if needed.
    int tail_start = n_vec4 * 4;
    int tail = n_total - tail_start;
    if (tail > 0) {
        int tb = (tail + 255) / 256;
        gather_tail_kernel<<<tb, 256>>>(index, values, out, tail_start, n_total);
    }
}

// round 14
// speedup vs baseline: 1.0390x; 1.0346x over previous
#include <cuda_runtime.h>
#include <cuda_bf16.h>
#include <cstdint>

// out[s,a] = values[index[s,a]]
// index: int32 [33,554,432], values: float [100], out: float [33,554,432]
//
// HBM-bound gather, converged at ~7.4 TB/s goodput. Last probe: NO smem table.
// The 400B values[] lives in 4 L1 lines (always hit after first touch);
// gather via __ldg removes the table fill + __syncthreads + smem footprint,
// making CTAs barrier-free. Memory pattern otherwise identical to the best
// config (128t, MLP=4 front-batched int4 loads, __ldcs/__stcs streaming).
//
// Sweep (kernel us): MLP=1 41.4 | 256t 37.1 | MLP=8 37.5 | 512t 38.0 |
// persistent 38.2 | repl-table 39.1 | 64t 36.22 | 128t+smem 36.19-36.93 (best)
// | stwb 36.99. Run-to-run variance of converged config ~±0.4us.

static constexpr int THREADS         = 128;
static constexpr int VEC_PER_THREAD  = 4;                        // 4 x int4 = 16 elems/thread
static constexpr int VEC_PER_BLOCK   = THREADS * VEC_PER_THREAD; // 512 vec4/block

__global__ void __launch_bounds__(THREADS) gather_nosmem_kernel(
    const int4* __restrict__ idx4,
    const float* __restrict__ values,
    float4* __restrict__ out4,
    int n_vec4)
{
    int base = blockIdx.x * VEC_PER_BLOCK + threadIdx.x;

    if (base + (VEC_PER_THREAD - 1) * THREADS < n_vec4) {
        // Fast path: every block for this shape (8,388,608 / 512 = 16384).
        int4 v[VEC_PER_THREAD];
        #pragma unroll
        for (int k = 0; k < VEC_PER_THREAD; k++) {
            v[k] = __ldcs(&idx4[base + k * THREADS]);
        }
        #pragma unroll
        for (int k = 0; k < VEC_PER_THREAD; k++) {
            float4 r;
            r.x = __ldg(&values[v[k].x]);
            r.y = __ldg(&values[v[k].y]);
            r.z = __ldg(&values[v[k].z]);
            r.w = __ldg(&values[v[k].w]);
            __stcs(&out4[base + k * THREADS], r);
        }
    } else {
        // Guard path (unused for this shape)
        #pragma unroll
        for (int k = 0; k < VEC_PER_THREAD; k++) {
            int i = base + k * THREADS;
            if (i < n_vec4) {
                int4 v = __ldcs(&idx4[i]);
                float4 r;
                r.x = __ldg(&values[v.x]);
                r.y = __ldg(&values[v.y]);
                r.z = __ldg(&values[v.z]);
                r.w = __ldg(&values[v.w]);
                __stcs(&out4[i], r);
            }
        }
    }
}

__global__ void gather_tail_kernel(
    const int* __restrict__ idx,
    const float* __restrict__ values,
    float* __restrict__ out,
    int start,
    int n_total)
{
    int i = start + blockIdx.x * blockDim.x + threadIdx.x;
    if (i < n_total) {
        out[i] = __ldg(&values[idx[i]]);
    }
}

extern "C" void kernel_launch(void* const* d_in, const int* in_sizes, int n_in,
                              void* d_out, int out_size)
{
    const int* index = (const int*)d_in[0];
    const float* values = (const float*)d_in[1];
    float* out = (float*)d_out;

    int n_total = in_sizes[0];          // 33,554,432
    int n_vec4 = n_total / 4;           // 8,388,608

    int blocks = (n_vec4 + VEC_PER_BLOCK - 1) / VEC_PER_BLOCK;   // 16384
    gather_nosmem_kernel<<<blocks, THREADS>>>(
        (const int4*)index, values, (float4*)out, n_vec4);

    // Tail is 0 for this shape (n_total % 4 == 0); launch only if needed.
    int tail_start = n_vec4 * 4;
    int tail = n_total - tail_start;
    if (tail > 0) {
        int tb = (tail + 255) / 256;
        gather_tail_kernel<<<tb, 256>>>(index, values, out, tail_start, n_total);
    }
}